// round 2
// baseline (speedup 1.0000x reference)
#include <cuda_runtime.h>
#include <cuda_bf16.h>
#include <math.h>

// Problem constants
#define BB  64      // batch
#define TT  12      // time steps (in = out)
#define NN  325     // nodes
#define DIN 2       // input dim
#define HH  128     // hidden
#define KF  5       // 1 + 2*ORDER diffusion features

// Derived max sizes
#define CMAX        256                       // max per-feature channel count (H+H)
#define NB          (NN*BB)                   // 20800 rows
#define FEATS_ELEMS (5LL*NN*BB*CMAX)          // 26,624,000
#define GATES_ELEMS ((long long)NB*2*HH)      // 5,324,800
#define H_ELEMS     ((long long)NB*HH)        // 2,662,400

// Scratch (static device globals; no allocation allowed)
__device__ float g_feats[FEATS_ELEMS];
__device__ float g_gates[GATES_ELEMS];
__device__ float g_hc[H_ELEMS];
__device__ float g_h0[H_ELEMS];
__device__ float g_h1[H_ELEMS];
__device__ float g_xdec[(long long)NB*DIN];

// ---------------------------------------------------------------------------
// Generic SGEMM: C[M x N] = act( sum_p A_p[M x Kpp] @ B[(p*Kpp..)(xN)] + bias )
// A address: A + p*pstrideA + row*lda + k   (planes let us treat the 5
// diffusion-feature blocks as one K=5C GEMM with register accumulation)
// B address: B[(p*Kpp + k)*ldb + col]
// act: 0 none, 1 sigmoid, 2 tanh
// ---------------------------------------------------------------------------
__global__ __launch_bounds__(256) void sgemm_kernel(
    int M, int N, int Kpp, int nplanes,
    const float* __restrict__ A, int lda, long long pstrideA,
    const float* __restrict__ B, int ldb,
    float* __restrict__ C, int ldc,
    const float* __restrict__ bias, int act)
{
    __shared__ float As[8][128];
    __shared__ float Bs[8][128];

    const int tid  = threadIdx.x;
    const int trow = tid >> 4;   // 0..15
    const int tcol = tid & 15;   // 0..15
    const int rowBase = blockIdx.y * 128;
    const int colBase = blockIdx.x * 128;

    float acc[8][8];
#pragma unroll
    for (int i = 0; i < 8; ++i)
#pragma unroll
        for (int j = 0; j < 8; ++j) acc[i][j] = 0.f;

    for (int p = 0; p < nplanes; ++p) {
        const float* Ap = A + (long long)p * pstrideA;
        const int kbase = p * Kpp;
        for (int k0 = 0; k0 < Kpp; k0 += 8) {
            // load A tile (128 rows x 8 k), store transposed As[k][row]
#pragma unroll
            for (int i = 0; i < 4; ++i) {
                int idx = tid + i * 256;
                int ar = idx >> 3, ak = idx & 7;
                int gr = rowBase + ar, gk = k0 + ak;
                float v = 0.f;
                if (gr < M && gk < Kpp) v = Ap[(long long)gr * lda + gk];
                As[ak][ar] = v;
            }
            // load B tile (8 k x 128 cols)
#pragma unroll
            for (int i = 0; i < 4; ++i) {
                int idx = tid + i * 256;
                int bk = idx >> 7, bc = idx & 127;
                int gk = k0 + bk, gc = colBase + bc;
                float v = 0.f;
                if (gk < Kpp && gc < N) v = B[(long long)(kbase + gk) * ldb + gc];
                Bs[bk][bc] = v;
            }
            __syncthreads();
#pragma unroll
            for (int kk = 0; kk < 8; ++kk) {
                float a[8], b[8];
#pragma unroll
                for (int i = 0; i < 8; ++i) a[i] = As[kk][trow * 8 + i];
#pragma unroll
                for (int j = 0; j < 8; ++j) b[j] = Bs[kk][tcol * 8 + j];
#pragma unroll
                for (int i = 0; i < 8; ++i)
#pragma unroll
                    for (int j = 0; j < 8; ++j) acc[i][j] += a[i] * b[j];
            }
            __syncthreads();
        }
    }

#pragma unroll
    for (int i = 0; i < 8; ++i) {
        int gr = rowBase + trow * 8 + i;
        if (gr >= M) continue;
#pragma unroll
        for (int j = 0; j < 8; ++j) {
            int gc = colBase + tcol * 8 + j;
            if (gc >= N) continue;
            float v = acc[i][j];
            if (bias) v += bias[gc];
            if (act == 1)      v = 1.f / (1.f + expf(-v));
            else if (act == 2) v = tanhf(v);
            C[(long long)gr * ldc + gc] = v;
        }
    }
}

// ---------------------------------------------------------------------------
// Build plane 0 of feats: [x, (r*)h] in (n, b, c) layout.
// xmode 0: x from source tensor (B,T,N,DIN) at time t;  xmode 1: x from a
// plane-layout buffer (row nb, Cx cols). useR multiplies h by r from gates.
// ---------------------------------------------------------------------------
__global__ void concat_kernel(float* __restrict__ plane0,
                              const float* __restrict__ xsrc, int xmode, int t, int Cx,
                              const float* __restrict__ h,
                              const float* __restrict__ gates, int useR)
{
    const int C = Cx + HH;
    const long long total = (long long)NN * BB * C;
    for (long long i = blockIdx.x * (long long)blockDim.x + threadIdx.x; i < total;
         i += (long long)gridDim.x * blockDim.x) {
        int c  = (int)(i % C);
        int nb = (int)(i / C);
        float v;
        if (c < Cx) {
            if (xmode == 0) {
                int b = nb % BB, n = nb / BB;
                v = xsrc[(((long long)b * TT + t) * NN + n) * DIN + c];
            } else {
                v = xsrc[(long long)nb * Cx + c];
            }
        } else {
            int hc = c - Cx;
            float hv = h[(long long)nb * HH + hc];
            if (useR) hv *= gates[(long long)nb * (2 * HH) + HH + hc];
            v = hv;
        }
        plane0[i] = v;
    }
}

// h = z*h + (1-z)*hc   (z = first H columns of gates)
__global__ void gru_update_kernel(float* __restrict__ h,
                                  const float* __restrict__ gates,
                                  const float* __restrict__ hcb)
{
    int i = blockIdx.x * blockDim.x + threadIdx.x;
    if (i >= NN * BB * HH) return;
    int row = i / HH, c = i % HH;
    float z = gates[(long long)row * (2 * HH) + c];
    h[i] = z * h[i] + (1.f - z) * hcb[i];
}

// Decoder output projection: y = h1 @ Wp + bp, scattered to out (B,T,N,2) and
// to xdec (plane layout) as next decoder input.
__global__ void dec_proj_kernel(const float* __restrict__ h1,
                                const float* __restrict__ Wp,
                                const float* __restrict__ bp,
                                float* __restrict__ out,
                                float* __restrict__ xdec, int t)
{
    int row = blockIdx.x * blockDim.x + threadIdx.x;
    if (row >= NN * BB) return;
    int n = row / BB, b = row % BB;
    float a0 = bp[0], a1 = bp[1];
    const float* hr = h1 + (long long)row * HH;
#pragma unroll 8
    for (int k = 0; k < HH; ++k) {
        float hv = hr[k];
        a0 += hv * Wp[k * 2 + 0];
        a1 += hv * Wp[k * 2 + 1];
    }
    long long o = (((long long)b * TT + t) * NN + n) * 2;
    out[o]     = a0;
    out[o + 1] = a1;
    xdec[(long long)row * 2]     = a0;
    xdec[(long long)row * 2 + 1] = a1;
}

__global__ void zero_kernel(float* __restrict__ p, long long n)
{
    for (long long i = blockIdx.x * (long long)blockDim.x + threadIdx.x; i < n;
         i += (long long)gridDim.x * blockDim.x)
        p[i] = 0.f;
}

// ---------------------------------------------------------------------------
// Host orchestration
// ---------------------------------------------------------------------------
static inline int gblocks(long long total, int tpb) {
    long long b = (total + tpb - 1) / tpb;
    if (b > 1048576) b = 1048576;
    return (int)b;
}

struct CellWeights { const float *Wg, *bg, *Wc, *bc; };

static void run_cell(const float* xsrc, int xmode, int t, int Cx,
                     float* h, const float* supports, const CellWeights& w,
                     float* feats, float* gates, float* hcb)
{
    const int C = Cx + HH;
    const long long NBC = (long long)NN * BB * C;
    const int cols = BB * C;
    const long long totalC = (long long)NN * BB * C;

    dim3 gS((cols + 127) / 128, (NN + 127) / 128);

    auto spmm = [&](const float* Sm, const float* src, float* dst) {
        sgemm_kernel<<<gS, 256>>>(NN, cols, NN, 1, Sm, NN, 0, src, cols, dst, cols,
                                  nullptr, 0);
    };

    // ---- gate gconv ----
    concat_kernel<<<gblocks(totalC, 256), 256>>>(feats, xsrc, xmode, t, Cx, h,
                                                 nullptr, 0);
    spmm(supports,             feats,           feats + 1 * NBC);
    spmm(supports,             feats + 1 * NBC, feats + 2 * NBC);
    spmm(supports + NN * NN,   feats,           feats + 3 * NBC);
    spmm(supports + NN * NN,   feats + 3 * NBC, feats + 4 * NBC);
    {
        dim3 g((2 * HH + 127) / 128, (NB + 127) / 128);
        sgemm_kernel<<<g, 256>>>(NB, 2 * HH, C, KF, feats, C, NBC, w.Wg, 2 * HH,
                                 gates, 2 * HH, w.bg, 1 /*sigmoid*/);
    }

    // ---- candidate gconv (input = [x, r*h]) ----
    concat_kernel<<<gblocks(totalC, 256), 256>>>(feats, xsrc, xmode, t, Cx, h,
                                                 gates, 1);
    spmm(supports,             feats,           feats + 1 * NBC);
    spmm(supports,             feats + 1 * NBC, feats + 2 * NBC);
    spmm(supports + NN * NN,   feats,           feats + 3 * NBC);
    spmm(supports + NN * NN,   feats + 3 * NBC, feats + 4 * NBC);
    {
        dim3 g((HH + 127) / 128, (NB + 127) / 128);
        sgemm_kernel<<<g, 256>>>(NB, HH, C, KF, feats, C, NBC, w.Wc, HH,
                                 hcb, HH, w.bc, 2 /*tanh*/);
    }

    // ---- GRU update ----
    gru_update_kernel<<<gblocks((long long)NB * HH, 256), 256>>>(h, gates, hcb);
}

extern "C" void kernel_launch(void* const* d_in, const int* in_sizes, int n_in,
                              void* d_out, int out_size)
{
    const float* source   = (const float*)d_in[0];
    // d_in[1] = targets (only defines T_out, unused numerically)
    const float* supports = (const float*)d_in[2];
    CellWeights enc0{ (const float*)d_in[3],  (const float*)d_in[4],
                      (const float*)d_in[5],  (const float*)d_in[6] };
    CellWeights enc1{ (const float*)d_in[7],  (const float*)d_in[8],
                      (const float*)d_in[9],  (const float*)d_in[10] };
    CellWeights dec0{ (const float*)d_in[11], (const float*)d_in[12],
                      (const float*)d_in[13], (const float*)d_in[14] };
    CellWeights dec1{ (const float*)d_in[15], (const float*)d_in[16],
                      (const float*)d_in[17], (const float*)d_in[18] };
    const float* Wp = (const float*)d_in[19];
    const float* bp = (const float*)d_in[20];
    float* out = (float*)d_out;

    float *feats, *gates, *hcb, *h0, *h1, *xdec;
    cudaGetSymbolAddress((void**)&feats, g_feats);
    cudaGetSymbolAddress((void**)&gates, g_gates);
    cudaGetSymbolAddress((void**)&hcb,   g_hc);
    cudaGetSymbolAddress((void**)&h0,    g_h0);
    cudaGetSymbolAddress((void**)&h1,    g_h1);
    cudaGetSymbolAddress((void**)&xdec,  g_xdec);

    // deterministic init each call
    zero_kernel<<<gblocks(H_ELEMS, 256), 256>>>(h0, H_ELEMS);
    zero_kernel<<<gblocks(H_ELEMS, 256), 256>>>(h1, H_ELEMS);
    zero_kernel<<<gblocks((long long)NB * DIN, 256), 256>>>(xdec, (long long)NB * DIN);

    // ---- encoder (interleaved layers: layer1 at step t only needs layer0@t) ----
    for (int t = 0; t < TT; ++t) {
        run_cell(source, 0, t, DIN, h0, supports, enc0, feats, gates, hcb);
        run_cell(h0,     1, t, HH,  h1, supports, enc1, feats, gates, hcb);
    }

    // ---- decoder (states continue from encoder finals in h0/h1) ----
    for (int t = 0; t < TT; ++t) {
        run_cell(xdec, 1, t, DIN, h0, supports, dec0, feats, gates, hcb);
        run_cell(h0,   1, t, HH,  h1, supports, dec1, feats, gates, hcb);
        dec_proj_kernel<<<(NB + 255) / 256, 256>>>(h1, Wp, bp, out, xdec, t);
    }
}

// round 3
// speedup vs baseline: 1.6614x; 1.6614x over previous
#include <cuda_runtime.h>
#include <cuda_bf16.h>
#include <mma.h>
#include <math.h>

using namespace nvcuda;

// Problem constants
#define BB  64      // batch
#define TT  12      // time steps (in = out)
#define NN  325     // nodes
#define DIN 2       // input dim
#define HH  128     // hidden
#define KF  5       // 1 + 2*ORDER diffusion features

// Derived max sizes
#define CMAX        256
#define NB          (NN*BB)                   // 20800 rows
#define FEATS_ELEMS (5LL*NN*BB*CMAX)
#define GATES_ELEMS ((long long)NB*2*HH)
#define H_ELEMS     ((long long)NB*HH)

// Scratch (static device globals; no allocation allowed)
__device__ float g_feats[FEATS_ELEMS];
__device__ float g_gates[GATES_ELEMS];
__device__ float g_hc[H_ELEMS];
__device__ float g_h0[H_ELEMS];
__device__ float g_h1[H_ELEMS];
__device__ float g_xdec[(long long)NB*DIN];

// ---------------------------------------------------------------------------
// Tensor-core GEMM (bf16 hi/lo split, fp32 accumulate, 3 MMAs per product):
//   C[M x N] = act( sum_p A_p[M x Kpp] @ B[(p*Kpp..) x N] + bias )
// Block tile 128x128, K-tile 32, 8 warps (2 x 4), warp tile 64x32,
// wmma 16x16x16 bf16. act: 0 none, 1 sigmoid, 2 tanh.
// ---------------------------------------------------------------------------
#define BM 128
#define BN 128
#define BK 32
#define APAD 8
#define BPAD 8

__global__ __launch_bounds__(256) void wgemm_kernel(
    int M, int N, int Kpp, int nplanes,
    const float* __restrict__ A, int lda, long long pstrideA,
    const float* __restrict__ B, int ldb,
    float* __restrict__ C, int ldc,
    const float* __restrict__ bias, int act)
{
    __shared__ __nv_bfloat16 sAh[BM][BK + APAD];   // 10240 B
    __shared__ __nv_bfloat16 sAl[BM][BK + APAD];   // 10240 B
    __shared__ __nv_bfloat16 sBh[BK][BN + BPAD];   //  8704 B
    __shared__ __nv_bfloat16 sBl[BK][BN + BPAD];   //  8704 B
    __shared__ float sEpi[8][256];                 //  8192 B  (per-warp epilogue)

    const int tid = threadIdx.x;
    const int w   = tid >> 5;          // warp 0..7
    const int wm  = w >> 2;            // 0..1  (64 rows each)
    const int wn  = w & 3;             // 0..3  (32 cols each)
    const int lane = tid & 31;
    const int rowBase = blockIdx.y * BM;
    const int colBase = blockIdx.x * BN;

    wmma::fragment<wmma::accumulator, 16, 16, 16, float> acc[4][2];
#pragma unroll
    for (int i = 0; i < 4; ++i)
#pragma unroll
        for (int j = 0; j < 2; ++j) wmma::fill_fragment(acc[i][j], 0.f);

    for (int p = 0; p < nplanes; ++p) {
        const float* Ap = A + (long long)p * pstrideA;
        const int kbase = p * Kpp;
        for (int k0 = 0; k0 < Kpp; k0 += BK) {
            // ---- load + split A tile: 128 x 32 ----
#pragma unroll
            for (int t = 0; t < 16; ++t) {
                int idx = tid + t * 256;
                int ar = idx >> 5, ak = idx & 31;
                int gr = rowBase + ar, gk = k0 + ak;
                float v = 0.f;
                if (gr < M && gk < Kpp) v = Ap[(long long)gr * lda + gk];
                __nv_bfloat16 hi = __float2bfloat16_rn(v);
                __nv_bfloat16 lo = __float2bfloat16_rn(v - __bfloat162float(hi));
                sAh[ar][ak] = hi;
                sAl[ar][ak] = lo;
            }
            // ---- load + split B tile: 32 x 128 ----
#pragma unroll
            for (int t = 0; t < 16; ++t) {
                int idx = tid + t * 256;
                int bk = idx >> 7, bc = idx & 127;
                int gk = k0 + bk, gc = colBase + bc;
                float v = 0.f;
                if (gk < Kpp && gc < N) v = B[(long long)(kbase + gk) * ldb + gc];
                __nv_bfloat16 hi = __float2bfloat16_rn(v);
                __nv_bfloat16 lo = __float2bfloat16_rn(v - __bfloat162float(hi));
                sBh[bk][bc] = hi;
                sBl[bk][bc] = lo;
            }
            __syncthreads();

#pragma unroll
            for (int kk = 0; kk < BK; kk += 16) {
                wmma::fragment<wmma::matrix_a, 16, 16, 16, __nv_bfloat16, wmma::row_major> ah[4], al[4];
                wmma::fragment<wmma::matrix_b, 16, 16, 16, __nv_bfloat16, wmma::row_major> bh[2], bl[2];
#pragma unroll
                for (int i = 0; i < 4; ++i) {
                    wmma::load_matrix_sync(ah[i], &sAh[wm * 64 + i * 16][kk], BK + APAD);
                    wmma::load_matrix_sync(al[i], &sAl[wm * 64 + i * 16][kk], BK + APAD);
                }
#pragma unroll
                for (int j = 0; j < 2; ++j) {
                    wmma::load_matrix_sync(bh[j], &sBh[kk][wn * 32 + j * 16], BN + BPAD);
                    wmma::load_matrix_sync(bl[j], &sBl[kk][wn * 32 + j * 16], BN + BPAD);
                }
#pragma unroll
                for (int i = 0; i < 4; ++i)
#pragma unroll
                    for (int j = 0; j < 2; ++j) {
                        wmma::mma_sync(acc[i][j], ah[i], bh[j], acc[i][j]);
                        wmma::mma_sync(acc[i][j], ah[i], bl[j], acc[i][j]);
                        wmma::mma_sync(acc[i][j], al[i], bh[j], acc[i][j]);
                    }
            }
            __syncthreads();
        }
    }

    // ---- epilogue: per-warp 16x16 round-trip through smem for bias+act ----
#pragma unroll
    for (int i = 0; i < 4; ++i)
#pragma unroll
        for (int j = 0; j < 2; ++j) {
            wmma::store_matrix_sync(&sEpi[w][0], acc[i][j], 16, wmma::mem_row_major);
            __syncwarp();
#pragma unroll
            for (int t = 0; t < 8; ++t) {
                int e = t * 32 + lane;
                int r = e >> 4, c = e & 15;
                int gr = rowBase + wm * 64 + i * 16 + r;
                int gc = colBase + wn * 32 + j * 16 + c;
                if (gr < M && gc < N) {
                    float v = sEpi[w][e];
                    if (bias) v += bias[gc];
                    if (act == 1)      v = 1.f / (1.f + expf(-v));
                    else if (act == 2) v = tanhf(v);
                    C[(long long)gr * ldc + gc] = v;
                }
            }
            __syncwarp();
        }
}

// ---------------------------------------------------------------------------
// Build plane 0 of feats: [x, (r*)h] in (n, b, c) layout.
// ---------------------------------------------------------------------------
__global__ void concat_kernel(float* __restrict__ plane0,
                              const float* __restrict__ xsrc, int xmode, int t, int Cx,
                              const float* __restrict__ h,
                              const float* __restrict__ gates, int useR)
{
    const int C = Cx + HH;
    const long long total = (long long)NN * BB * C;
    for (long long i = blockIdx.x * (long long)blockDim.x + threadIdx.x; i < total;
         i += (long long)gridDim.x * blockDim.x) {
        int c  = (int)(i % C);
        int nb = (int)(i / C);
        float v;
        if (c < Cx) {
            if (xmode == 0) {
                int b = nb % BB, n = nb / BB;
                v = xsrc[(((long long)b * TT + t) * NN + n) * DIN + c];
            } else {
                v = xsrc[(long long)nb * Cx + c];
            }
        } else {
            int hc = c - Cx;
            float hv = h[(long long)nb * HH + hc];
            if (useR) hv *= gates[(long long)nb * (2 * HH) + HH + hc];
            v = hv;
        }
        plane0[i] = v;
    }
}

// h = z*h + (1-z)*hc
__global__ void gru_update_kernel(float* __restrict__ h,
                                  const float* __restrict__ gates,
                                  const float* __restrict__ hcb)
{
    int i = blockIdx.x * blockDim.x + threadIdx.x;
    if (i >= NN * BB * HH) return;
    int row = i / HH, c = i % HH;
    float z = gates[(long long)row * (2 * HH) + c];
    h[i] = z * h[i] + (1.f - z) * hcb[i];
}

// Decoder output projection: y = h1 @ Wp + bp
__global__ void dec_proj_kernel(const float* __restrict__ h1,
                                const float* __restrict__ Wp,
                                const float* __restrict__ bp,
                                float* __restrict__ out,
                                float* __restrict__ xdec, int t)
{
    int row = blockIdx.x * blockDim.x + threadIdx.x;
    if (row >= NN * BB) return;
    int n = row / BB, b = row % BB;
    float a0 = bp[0], a1 = bp[1];
    const float* hr = h1 + (long long)row * HH;
#pragma unroll 8
    for (int k = 0; k < HH; ++k) {
        float hv = hr[k];
        a0 += hv * Wp[k * 2 + 0];
        a1 += hv * Wp[k * 2 + 1];
    }
    long long o = (((long long)b * TT + t) * NN + n) * 2;
    out[o]     = a0;
    out[o + 1] = a1;
    xdec[(long long)row * 2]     = a0;
    xdec[(long long)row * 2 + 1] = a1;
}

__global__ void zero_kernel(float* __restrict__ p, long long n)
{
    for (long long i = blockIdx.x * (long long)blockDim.x + threadIdx.x; i < n;
         i += (long long)gridDim.x * blockDim.x)
        p[i] = 0.f;
}

// ---------------------------------------------------------------------------
// Host orchestration
// ---------------------------------------------------------------------------
static inline int gblocks(long long total, int tpb) {
    long long b = (total + tpb - 1) / tpb;
    if (b > 1048576) b = 1048576;
    return (int)b;
}

struct CellWeights { const float *Wg, *bg, *Wc, *bc; };

static void run_cell(const float* xsrc, int xmode, int t, int Cx,
                     float* h, const float* supports, const CellWeights& w,
                     float* feats, float* gates, float* hcb)
{
    const int C = Cx + HH;
    const long long NBC = (long long)NN * BB * C;
    const int cols = BB * C;
    const long long totalC = (long long)NN * BB * C;

    dim3 gS((cols + BN - 1) / BN, (NN + BM - 1) / BM);

    auto spmm = [&](const float* Sm, const float* src, float* dst) {
        wgemm_kernel<<<gS, 256>>>(NN, cols, NN, 1, Sm, NN, 0, src, cols, dst, cols,
                                  nullptr, 0);
    };

    // ---- gate gconv ----
    concat_kernel<<<gblocks(totalC, 256), 256>>>(feats, xsrc, xmode, t, Cx, h,
                                                 nullptr, 0);
    spmm(supports,             feats,           feats + 1 * NBC);
    spmm(supports,             feats + 1 * NBC, feats + 2 * NBC);
    spmm(supports + NN * NN,   feats,           feats + 3 * NBC);
    spmm(supports + NN * NN,   feats + 3 * NBC, feats + 4 * NBC);
    {
        dim3 g((2 * HH + BN - 1) / BN, (NB + BM - 1) / BM);
        wgemm_kernel<<<g, 256>>>(NB, 2 * HH, C, KF, feats, C, NBC, w.Wg, 2 * HH,
                                 gates, 2 * HH, w.bg, 1 /*sigmoid*/);
    }

    // ---- candidate gconv (input = [x, r*h]) ----
    concat_kernel<<<gblocks(totalC, 256), 256>>>(feats, xsrc, xmode, t, Cx, h,
                                                 gates, 1);
    spmm(supports,             feats,           feats + 1 * NBC);
    spmm(supports,             feats + 1 * NBC, feats + 2 * NBC);
    spmm(supports + NN * NN,   feats,           feats + 3 * NBC);
    spmm(supports + NN * NN,   feats + 3 * NBC, feats + 4 * NBC);
    {
        dim3 g((HH + BN - 1) / BN, (NB + BM - 1) / BM);
        wgemm_kernel<<<g, 256>>>(NB, HH, C, KF, feats, C, NBC, w.Wc, HH,
                                 hcb, HH, w.bc, 2 /*tanh*/);
    }

    // ---- GRU update ----
    gru_update_kernel<<<gblocks((long long)NB * HH, 256), 256>>>(h, gates, hcb);
}

extern "C" void kernel_launch(void* const* d_in, const int* in_sizes, int n_in,
                              void* d_out, int out_size)
{
    const float* source   = (const float*)d_in[0];
    const float* supports = (const float*)d_in[2];
    CellWeights enc0{ (const float*)d_in[3],  (const float*)d_in[4],
                      (const float*)d_in[5],  (const float*)d_in[6] };
    CellWeights enc1{ (const float*)d_in[7],  (const float*)d_in[8],
                      (const float*)d_in[9],  (const float*)d_in[10] };
    CellWeights dec0{ (const float*)d_in[11], (const float*)d_in[12],
                      (const float*)d_in[13], (const float*)d_in[14] };
    CellWeights dec1{ (const float*)d_in[15], (const float*)d_in[16],
                      (const float*)d_in[17], (const float*)d_in[18] };
    const float* Wp = (const float*)d_in[19];
    const float* bp = (const float*)d_in[20];
    float* out = (float*)d_out;

    float *feats, *gates, *hcb, *h0, *h1, *xdec;
    cudaGetSymbolAddress((void**)&feats, g_feats);
    cudaGetSymbolAddress((void**)&gates, g_gates);
    cudaGetSymbolAddress((void**)&hcb,   g_hc);
    cudaGetSymbolAddress((void**)&h0,    g_h0);
    cudaGetSymbolAddress((void**)&h1,    g_h1);
    cudaGetSymbolAddress((void**)&xdec,  g_xdec);

    // deterministic init each call
    zero_kernel<<<gblocks(H_ELEMS, 256), 256>>>(h0, H_ELEMS);
    zero_kernel<<<gblocks(H_ELEMS, 256), 256>>>(h1, H_ELEMS);
    zero_kernel<<<gblocks((long long)NB * DIN, 256), 256>>>(xdec, (long long)NB * DIN);

    // ---- encoder ----
    for (int t = 0; t < TT; ++t) {
        run_cell(source, 0, t, DIN, h0, supports, enc0, feats, gates, hcb);
        run_cell(h0,     1, t, HH,  h1, supports, enc1, feats, gates, hcb);
    }

    // ---- decoder ----
    for (int t = 0; t < TT; ++t) {
        run_cell(xdec, 1, t, DIN, h0, supports, dec0, feats, gates, hcb);
        run_cell(h0,   1, t, HH,  h1, supports, dec1, feats, gates, hcb);
        dec_proj_kernel<<<(NB + 255) / 256, 256>>>(h1, Wp, bp, out, xdec, t);
    }
}

// round 5
// speedup vs baseline: 2.6224x; 1.5785x over previous
#include <cuda_runtime.h>
#include <cuda_bf16.h>
#include <mma.h>
#include <math.h>
#include <stdint.h>

using namespace nvcuda;

// Problem constants
#define BB  64
#define TT  12
#define NN  325
#define DIN 2
#define HH  128
#define KF  5

#define NB      (NN*BB)          // 20800
#define CP0     144              // padded C for layer0 (130 -> 144)
#define CP1     256              // layer1 C
#define KTB0    192              // weight K rows per plane, layer0 (ceil64(144))
#define KTB1    256

#define PSTR0   (384LL*64*144)   // 3,538,944
#define PSTR1   (384LL*64*256)   // 6,291,456

// ---------------- static scratch (pads never written => stay zero) ----------
__device__ __align__(256) __nv_bfloat16 g_f0h[5*3538944], g_f0l[5*3538944];
__device__ __align__(256) __nv_bfloat16 g_f1h[5*6291456], g_f1l[5*6291456];
__device__ __align__(256) __nv_bfloat16 g_sh[2*384*384],  g_sl[2*384*384];
__device__ __align__(256) __nv_bfloat16 g_wh[1720320],    g_wl[1720320];
__device__ float g_gates[(long long)NB*2*HH];
__device__ float g_hc[(long long)NB*HH];
__device__ float g_h0[(long long)NB*HH];
__device__ float g_h1[(long long)NB*HH];
__device__ float g_xdec[(long long)NB*DIN];

// host-side cached device pointers for the split supports
static __nv_bfloat16 *g_sh_p = nullptr, *g_sl_p = nullptr;

// weight pool offsets
#define OFF_E0G 0
#define OFF_E0C 245760
#define OFF_E1G 368640
#define OFF_E1C 696320
#define OFF_D0G 860160
#define OFF_D0C 1105920
#define OFF_D1G 1228800
#define OFF_D1C 1556480

// ---------------------------------------------------------------------------
// prep kernels
// ---------------------------------------------------------------------------
__device__ __forceinline__ void split2(float v, __nv_bfloat16& hi, __nv_bfloat16& lo) {
    hi = __float2bfloat16_rn(v);
    lo = __float2bfloat16_rn(v - __bfloat162float(hi));
}

__global__ void split_supports_kernel(const float* __restrict__ sup) {
    int i = blockIdx.x * blockDim.x + threadIdx.x;
    if (i >= 2 * NN * NN) return;
    int s = i / (NN * NN), r = (i / NN) % NN, c = i % NN;
    __nv_bfloat16 hi, lo; split2(sup[i], hi, lo);
    long long d = (long long)s * 384 * 384 + (long long)r * 384 + c;
    g_sh[d] = hi; g_sl[d] = lo;
}

__global__ void split_weights_kernel(const float* __restrict__ W,
                                     __nv_bfloat16* __restrict__ dh,
                                     __nv_bfloat16* __restrict__ dl,
                                     int C, int KTB, int out) {
    int i = blockIdx.x * blockDim.x + threadIdx.x;
    if (i >= KF * C * out) return;
    int p = i / (C * out), rem = i % (C * out);
    int k = rem / out, c = rem % out;
    __nv_bfloat16 hi, lo; split2(W[i], hi, lo);
    long long d = ((long long)p * KTB + k) * out + c;
    dh[d] = hi; dl[d] = lo;
}

// ---------------------------------------------------------------------------
// Pipelined bf16-pair GEMM.  C = act( sum_p A_p @ B_p + bias )
// A: [M x Kt] rows (plane stride pstrA), values hi/lo, zero-padded.
// B: [Kt x N] (plane stride pstrB), zero-padded. BM=64, BN=128, BK=64.
// Output: pair (Ch,Cl) or fp32 Cf. blockIdx.z adds aZ/bZ/cZ offsets.
// ---------------------------------------------------------------------------
#define SMEM_A_BYTES 36864            // 2 stages * 2(hl) * 64 * 72 * 2B
#define SMEM_B_BYTES 69632            // 2 stages * 2(hl) * 64 * 136 * 2B
#define SMEM_TOTAL   (SMEM_A_BYTES + SMEM_B_BYTES)

__device__ __forceinline__ void cp16(uint32_t s, const void* g) {
    asm volatile("cp.async.cg.shared.global [%0], [%1], 16;\n" :: "r"(s), "l"(g));
}

__global__ __launch_bounds__(256, 2) void pgemm_kernel(
    int M, int Kt, int ktpp, int nplanes,
    const __nv_bfloat16* __restrict__ Ah, const __nv_bfloat16* __restrict__ Al,
    long long ldaA, long long pstrA, long long aZ,
    const __nv_bfloat16* __restrict__ Bh, const __nv_bfloat16* __restrict__ Bl,
    long long ldbB, long long pstrB, long long bZ,
    float* __restrict__ Cf, __nv_bfloat16* __restrict__ Ch, __nv_bfloat16* __restrict__ Cl,
    long long ldc, long long cZ,
    const float* __restrict__ bias, int act)
{
    extern __shared__ char smem[];
    __nv_bfloat16* sA = (__nv_bfloat16*)smem;
    __nv_bfloat16* sB = (__nv_bfloat16*)(smem + SMEM_A_BYTES);
    const uint32_t sAu = (uint32_t)__cvta_generic_to_shared(sA);
    const uint32_t sBu = (uint32_t)__cvta_generic_to_shared(sB);

    const int tid = threadIdx.x;
    const int w = tid >> 5, lane = tid & 31;
    const int wm = w >> 2, wn = w & 3;      // 2x4 warps, 32x32 tiles
    const int rowBase = blockIdx.y * 64;
    const int colBase = blockIdx.x * 128;

    Ah += (long long)blockIdx.z * aZ;  Al += (long long)blockIdx.z * aZ;
    Bh += (long long)blockIdx.z * bZ;  Bl += (long long)blockIdx.z * bZ;
    if (Ch) { Ch += (long long)blockIdx.z * cZ; Cl += (long long)blockIdx.z * cZ; }
    if (Cf) { Cf += (long long)blockIdx.z * cZ; }

    auto fill = [&](int stage, int it) {
        int p = it / ktpp;
        int k0 = (it - p * ktpp) * 64;
        const __nv_bfloat16* A0h = Ah + (long long)p * pstrA;
        const __nv_bfloat16* A0l = Al + (long long)p * pstrA;
        const __nv_bfloat16* B0h = Bh + (long long)p * pstrB;
        const __nv_bfloat16* B0l = Bl + (long long)p * pstrB;
#pragma unroll
        for (int t = 0; t < 2; ++t) {                 // A: 512 16B chunks per h/l
            int id = tid + t * 256;
            int row = id >> 3, cc = id & 7;
            int k = k0 + cc * 8;
            uint32_t s0 = sAu + (uint32_t)((((stage * 2 + 0) * 64 + row) * 72 + cc * 8) * 2);
            uint32_t s1 = sAu + (uint32_t)((((stage * 2 + 1) * 64 + row) * 72 + cc * 8) * 2);
            if (k < Kt) {
                long long ga = (long long)(rowBase + row) * ldaA + k;
                cp16(s0, A0h + ga);
                cp16(s1, A0l + ga);
            } else {
                float4 z = {0.f, 0.f, 0.f, 0.f};
                *(float4*)(sA + (((stage * 2 + 0) * 64 + row) * 72 + cc * 8)) = z;
                *(float4*)(sA + (((stage * 2 + 1) * 64 + row) * 72 + cc * 8)) = z;
            }
        }
#pragma unroll
        for (int t = 0; t < 4; ++t) {                 // B: 1024 16B chunks per h/l
            int id = tid + t * 256;
            int row = id >> 4, cc = id & 15;
            long long gb = (long long)(k0 + row) * ldbB + colBase + cc * 8;
            uint32_t s0 = sBu + (uint32_t)((((stage * 2 + 0) * 64 + row) * 136 + cc * 8) * 2);
            uint32_t s1 = sBu + (uint32_t)((((stage * 2 + 1) * 64 + row) * 136 + cc * 8) * 2);
            cp16(s0, B0h + gb);
            cp16(s1, B0l + gb);
        }
        asm volatile("cp.async.commit_group;\n" ::: "memory");
    };

    wmma::fragment<wmma::accumulator, 16, 16, 16, float> acc[2][2];
#pragma unroll
    for (int i = 0; i < 2; ++i)
#pragma unroll
        for (int j = 0; j < 2; ++j) wmma::fill_fragment(acc[i][j], 0.f);

    const int T = ktpp * nplanes;
    fill(0, 0);
    for (int it = 0; it < T; ++it) {
        if (it + 1 < T) {
            fill((it + 1) & 1, it + 1);
            asm volatile("cp.async.wait_group 1;\n" ::: "memory");
        } else {
            asm volatile("cp.async.wait_group 0;\n" ::: "memory");
        }
        __syncthreads();
        const int st = it & 1;
#pragma unroll
        for (int kk = 0; kk < 4; ++kk) {
            wmma::fragment<wmma::matrix_a, 16, 16, 16, __nv_bfloat16, wmma::row_major> a_h[2], a_l[2];
            wmma::fragment<wmma::matrix_b, 16, 16, 16, __nv_bfloat16, wmma::row_major> b_h[2], b_l[2];
#pragma unroll
            for (int i = 0; i < 2; ++i) {
                const int r = wm * 32 + i * 16;
                wmma::load_matrix_sync(a_h[i], sA + ((st * 2 + 0) * 64 + r) * 72 + kk * 16, 72);
                wmma::load_matrix_sync(a_l[i], sA + ((st * 2 + 1) * 64 + r) * 72 + kk * 16, 72);
            }
#pragma unroll
            for (int j = 0; j < 2; ++j) {
                const int c = wn * 32 + j * 16;
                wmma::load_matrix_sync(b_h[j], sB + ((st * 2 + 0) * 64 + kk * 16) * 136 + c, 136);
                wmma::load_matrix_sync(b_l[j], sB + ((st * 2 + 1) * 64 + kk * 16) * 136 + c, 136);
            }
#pragma unroll
            for (int i = 0; i < 2; ++i)
#pragma unroll
                for (int j = 0; j < 2; ++j) {
                    wmma::mma_sync(acc[i][j], a_h[i], b_h[j], acc[i][j]);
                    wmma::mma_sync(acc[i][j], a_h[i], b_l[j], acc[i][j]);
                    wmma::mma_sync(acc[i][j], a_l[i], b_h[j], acc[i][j]);
                }
        }
        __syncthreads();
    }

    // ---- epilogue: warp scratch (reuses sA region: 8 * 32*36 floats) ----
    float* scr = (float*)smem + w * (32 * 36);
#pragma unroll
    for (int i = 0; i < 2; ++i)
#pragma unroll
        for (int j = 0; j < 2; ++j)
            wmma::store_matrix_sync(scr + (i * 16) * 36 + j * 16, acc[i][j], 36,
                                    wmma::mem_row_major);
    __syncwarp();

#pragma unroll
    for (int t = 0; t < 16; ++t) {
        int e = lane + t * 32;
        int r = e >> 4, c = (e & 15) * 2;
        int gr = rowBase + wm * 32 + r;
        if (gr >= M) continue;
        int gc = colBase + wn * 32 + c;
        float v0 = scr[r * 36 + c];
        float v1 = scr[r * 36 + c + 1];
        if (bias) { v0 += bias[gc]; v1 += bias[gc + 1]; }
        if (act == 1) { v0 = 1.f / (1.f + expf(-v0)); v1 = 1.f / (1.f + expf(-v1)); }
        else if (act == 2) { v0 = tanhf(v0); v1 = tanhf(v1); }
        if (Ch) {
            __nv_bfloat16 h0, l0, h1, l1;
            split2(v0, h0, l0); split2(v1, h1, l1);
            __nv_bfloat162 hh; hh.x = h0; hh.y = h1;
            __nv_bfloat162 ll; ll.x = l0; ll.y = l1;
            *(__nv_bfloat162*)&Ch[(long long)gr * ldc + gc] = hh;
            *(__nv_bfloat162*)&Cl[(long long)gr * ldc + gc] = ll;
        } else {
            float2 f; f.x = v0; f.y = v1;
            *(float2*)&Cf[(long long)gr * ldc + gc] = f;
        }
    }
}

// ---------------------------------------------------------------------------
// Build plane 0 of feats (hi/lo): [x, (r*)h], zeros in pad columns.
// ---------------------------------------------------------------------------
__global__ void concat_kernel(__nv_bfloat16* __restrict__ ph,
                              __nv_bfloat16* __restrict__ pl,
                              const float* __restrict__ xsrc, int xmode, int t,
                              int Cx, int C, int Cp,
                              const float* __restrict__ h,
                              const float* __restrict__ gates, int useR)
{
    const long long total = (long long)NN * BB * Cp;
    for (long long i = blockIdx.x * (long long)blockDim.x + threadIdx.x; i < total;
         i += (long long)gridDim.x * blockDim.x) {
        int c  = (int)(i % Cp);
        int nb = (int)(i / Cp);
        float v = 0.f;
        if (c < Cx) {
            if (xmode == 0) {
                int b = nb % BB, n = nb / BB;
                v = xsrc[(((long long)b * TT + t) * NN + n) * DIN + c];
            } else {
                v = xsrc[(long long)nb * Cx + c];
            }
        } else if (c < C) {
            int hc = c - Cx;
            float hv = h[(long long)nb * HH + hc];
            if (useR) hv *= gates[(long long)nb * (2 * HH) + HH + hc];
            v = hv;
        }
        __nv_bfloat16 hi, lo; split2(v, hi, lo);
        ph[i] = hi; pl[i] = lo;
    }
}

__global__ void gru_update_kernel(float* __restrict__ h,
                                  const float* __restrict__ gates,
                                  const float* __restrict__ hcb)
{
    int i = blockIdx.x * blockDim.x + threadIdx.x;
    if (i >= NN * BB * HH) return;
    int row = i / HH, c = i % HH;
    float z = gates[(long long)row * (2 * HH) + c];
    h[i] = z * h[i] + (1.f - z) * hcb[i];
}

__global__ void dec_proj_kernel(const float* __restrict__ h1,
                                const float* __restrict__ Wp,
                                const float* __restrict__ bp,
                                float* __restrict__ out,
                                float* __restrict__ xdec, int t)
{
    int row = blockIdx.x * blockDim.x + threadIdx.x;
    if (row >= NN * BB) return;
    int n = row / BB, b = row % BB;
    float a0 = bp[0], a1 = bp[1];
    const float* hr = h1 + (long long)row * HH;
#pragma unroll 8
    for (int k = 0; k < HH; ++k) {
        float hv = hr[k];
        a0 += hv * Wp[k * 2 + 0];
        a1 += hv * Wp[k * 2 + 1];
    }
    long long o = (((long long)b * TT + t) * NN + n) * 2;
    out[o] = a0; out[o + 1] = a1;
    xdec[(long long)row * 2] = a0;
    xdec[(long long)row * 2 + 1] = a1;
}

__global__ void zero_kernel(float* __restrict__ p, long long n)
{
    for (long long i = blockIdx.x * (long long)blockDim.x + threadIdx.x; i < n;
         i += (long long)gridDim.x * blockDim.x)
        p[i] = 0.f;
}

// ---------------------------------------------------------------------------
// Host orchestration
// ---------------------------------------------------------------------------
static inline int gblocks(long long total, int tpb) {
    long long b = (total + tpb - 1) / tpb;
    if (b > 1048576) b = 1048576;
    return (int)b;
}

struct CellW {
    const __nv_bfloat16 *wgh, *wgl, *wch, *wcl;
    const float *bg, *bc;
    int Cx, C, Cp, ktpp, KTB;
    __nv_bfloat16 *fh, *fl;
    long long pstr;
};

static void run_cell(const float* xsrc, int xmode, int t, float* h,
                     const CellW& cw, float* gates, float* hcb)
{
    const int Cp = cw.Cp;
    const int ldN = BB * Cp;
    const long long PS = cw.pstr;
    const long long SUPZ = 384LL * 384;
    const long long totalC = (long long)NN * BB * Cp;

    dim3 gd(ldN / 128, 6, 2);

    auto diffuse = [&](const __nv_bfloat16* srcH, const __nv_bfloat16* srcL,
                       long long bZ, __nv_bfloat16* dstH, __nv_bfloat16* dstL) {
        pgemm_kernel<<<gd, 256, SMEM_TOTAL>>>(
            NN, 384, 6, 1,
            g_sh_p, g_sl_p, 384, 0, SUPZ,
            srcH, srcL, ldN, 0, bZ,
            nullptr, dstH, dstL, ldN, 2 * PS,
            nullptr, 0);
    };

    // ---- gate gconv ----
    concat_kernel<<<gblocks(totalC, 256), 256>>>(cw.fh, cw.fl, xsrc, xmode, t,
                                                 cw.Cx, cw.C, Cp, h, nullptr, 0);
    diffuse(cw.fh, cw.fl, 0, cw.fh + PS, cw.fl + PS);
    diffuse(cw.fh + PS, cw.fl + PS, 2 * PS, cw.fh + 2 * PS, cw.fl + 2 * PS);
    {
        dim3 g(2, NB / 64, 1);
        pgemm_kernel<<<g, 256, SMEM_TOTAL>>>(
            NB, Cp, cw.ktpp, KF,
            cw.fh, cw.fl, Cp, PS, 0,
            cw.wgh, cw.wgl, 2 * HH, (long long)cw.KTB * 2 * HH, 0,
            gates, nullptr, nullptr, 2 * HH, 0,
            cw.bg, 1);
    }

    // ---- candidate gconv ----
    concat_kernel<<<gblocks(totalC, 256), 256>>>(cw.fh, cw.fl, xsrc, xmode, t,
                                                 cw.Cx, cw.C, Cp, h, gates, 1);
    diffuse(cw.fh, cw.fl, 0, cw.fh + PS, cw.fl + PS);
    diffuse(cw.fh + PS, cw.fl + PS, 2 * PS, cw.fh + 2 * PS, cw.fl + 2 * PS);
    {
        dim3 g(1, NB / 64, 1);
        pgemm_kernel<<<g, 256, SMEM_TOTAL>>>(
            NB, Cp, cw.ktpp, KF,
            cw.fh, cw.fl, Cp, PS, 0,
            cw.wch, cw.wcl, HH, (long long)cw.KTB * HH, 0,
            hcb, nullptr, nullptr, HH, 0,
            cw.bc, 2);
    }

    gru_update_kernel<<<gblocks((long long)NB * HH, 256), 256>>>(h, gates, hcb);
}

extern "C" void kernel_launch(void* const* d_in, const int* in_sizes, int n_in,
                              void* d_out, int out_size)
{
    const float* source   = (const float*)d_in[0];
    const float* supports = (const float*)d_in[2];
    const float* Wp = (const float*)d_in[19];
    const float* bp = (const float*)d_in[20];
    float* out = (float*)d_out;

    cudaFuncSetAttribute(pgemm_kernel, cudaFuncAttributeMaxDynamicSharedMemorySize,
                         SMEM_TOTAL);

    __nv_bfloat16 *f0h, *f0l, *f1h, *f1l, *wh, *wl;
    float *gates, *hcb, *h0, *h1, *xdec;
    cudaGetSymbolAddress((void**)&f0h, g_f0h);
    cudaGetSymbolAddress((void**)&f0l, g_f0l);
    cudaGetSymbolAddress((void**)&f1h, g_f1h);
    cudaGetSymbolAddress((void**)&f1l, g_f1l);
    cudaGetSymbolAddress((void**)&g_sh_p, g_sh);
    cudaGetSymbolAddress((void**)&g_sl_p, g_sl);
    cudaGetSymbolAddress((void**)&wh, g_wh);
    cudaGetSymbolAddress((void**)&wl, g_wl);
    cudaGetSymbolAddress((void**)&gates, g_gates);
    cudaGetSymbolAddress((void**)&hcb, g_hc);
    cudaGetSymbolAddress((void**)&h0, g_h0);
    cudaGetSymbolAddress((void**)&h1, g_h1);
    cudaGetSymbolAddress((void**)&xdec, g_xdec);

    // ---- prep: split supports + weights to bf16 pairs (captured, cheap) ----
    split_supports_kernel<<<gblocks(2LL * NN * NN, 256), 256>>>(supports);
    struct WSpec { int in_idx, off, C, KTB, out; };
    const WSpec ws[8] = {
        {3,  OFF_E0G, 130, KTB0, 256}, {5,  OFF_E0C, 130, KTB0, 128},
        {7,  OFF_E1G, 256, KTB1, 256}, {9,  OFF_E1C, 256, KTB1, 128},
        {11, OFF_D0G, 130, KTB0, 256}, {13, OFF_D0C, 130, KTB0, 128},
        {15, OFF_D1G, 256, KTB1, 256}, {17, OFF_D1C, 256, KTB1, 128},
    };
    for (int i = 0; i < 8; ++i) {
        long long n = (long long)KF * ws[i].C * ws[i].out;
        split_weights_kernel<<<gblocks(n, 256), 256>>>(
            (const float*)d_in[ws[i].in_idx], wh + ws[i].off, wl + ws[i].off,
            ws[i].C, ws[i].KTB, ws[i].out);
    }

    zero_kernel<<<gblocks((long long)NB * HH, 256), 256>>>(h0, (long long)NB * HH);
    zero_kernel<<<gblocks((long long)NB * HH, 256), 256>>>(h1, (long long)NB * HH);
    zero_kernel<<<gblocks((long long)NB * DIN, 256), 256>>>(xdec, (long long)NB * DIN);

    CellW enc0{ wh + OFF_E0G, wl + OFF_E0G, wh + OFF_E0C, wl + OFF_E0C,
                (const float*)d_in[4],  (const float*)d_in[6],
                DIN, DIN + HH, CP0, 3, KTB0, f0h, f0l, PSTR0 };
    CellW enc1{ wh + OFF_E1G, wl + OFF_E1G, wh + OFF_E1C, wl + OFF_E1C,
                (const float*)d_in[8],  (const float*)d_in[10],
                HH, 2 * HH, CP1, 4, KTB1, f1h, f1l, PSTR1 };
    CellW dec0{ wh + OFF_D0G, wl + OFF_D0G, wh + OFF_D0C, wl + OFF_D0C,
                (const float*)d_in[12], (const float*)d_in[14],
                DIN, DIN + HH, CP0, 3, KTB0, f0h, f0l, PSTR0 };
    CellW dec1{ wh + OFF_D1G, wl + OFF_D1G, wh + OFF_D1C, wl + OFF_D1C,
                (const float*)d_in[16], (const float*)d_in[18],
                HH, 2 * HH, CP1, 4, KTB1, f1h, f1l, PSTR1 };

    for (int t = 0; t < TT; ++t) {
        run_cell(source, 0, t, h0, enc0, gates, hcb);
        run_cell(h0,     1, t, h1, enc1, gates, hcb);
    }
    for (int t = 0; t < TT; ++t) {
        run_cell(xdec, 1, t, h0, dec0, gates, hcb);
        run_cell(h0,   1, t, h1, dec1, gates, hcb);
        dec_proj_kernel<<<(NB + 255) / 256, 256>>>(h1, Wp, bp, out, xdec, t);
    }
}

// round 6
// speedup vs baseline: 2.6260x; 1.0014x over previous
#include <cuda_runtime.h>
#include <cuda_bf16.h>
#include <mma.h>
#include <math.h>
#include <stdint.h>

using namespace nvcuda;

// Problem constants
#define BB  64
#define TT  12
#define NN  325
#define DIN 2
#define HH  128
#define KF  5

#define NB      (NN*BB)          // 20800
#define CP0     144              // padded C for layer0 (130 -> 144)
#define CP1     256              // layer1 C
#define KTB0    192              // weight K rows per plane, layer0 (ceil64(144))
#define KTB1    256

#define PSTR0   (384LL*64*144)   // 3,538,944
#define PSTR1   (384LL*64*256)   // 6,291,456

// ---------------- static scratch (pads never written => stay zero) ----------
__device__ __align__(256) __nv_bfloat16 g_f0h[5*3538944], g_f0l[5*3538944];
__device__ __align__(256) __nv_bfloat16 g_f1h[5*6291456], g_f1l[5*6291456];
__device__ __align__(256) __nv_bfloat16 g_sh[2*384*384],  g_sl[2*384*384];
__device__ __align__(256) __nv_bfloat16 g_wh[1720320],    g_wl[1720320];
__device__ float g_gates[(long long)NB*2*HH];
__device__ float g_hc[(long long)NB*HH];
__device__ float g_h0[(long long)NB*HH];
__device__ float g_h1[(long long)NB*HH];
__device__ float g_xdec[(long long)NB*DIN];

// host-side cached device pointers for the split supports
static __nv_bfloat16 *g_sh_p = nullptr, *g_sl_p = nullptr;

// weight pool offsets
#define OFF_E0G 0
#define OFF_E0C 245760
#define OFF_E1G 368640
#define OFF_E1C 696320
#define OFF_D0G 860160
#define OFF_D0C 1105920
#define OFF_D1G 1228800
#define OFF_D1C 1556480

// ---------------------------------------------------------------------------
// prep kernels
// ---------------------------------------------------------------------------
__device__ __forceinline__ void split2(float v, __nv_bfloat16& hi, __nv_bfloat16& lo) {
    hi = __float2bfloat16_rn(v);
    lo = __float2bfloat16_rn(v - __bfloat162float(hi));
}

__global__ void split_supports_kernel(const float* __restrict__ sup) {
    int i = blockIdx.x * blockDim.x + threadIdx.x;
    if (i >= 2 * NN * NN) return;
    int s = i / (NN * NN), r = (i / NN) % NN, c = i % NN;
    __nv_bfloat16 hi, lo; split2(sup[i], hi, lo);
    long long d = (long long)s * 384 * 384 + (long long)r * 384 + c;
    g_sh[d] = hi; g_sl[d] = lo;
}

__global__ void split_weights_kernel(const float* __restrict__ W,
                                     __nv_bfloat16* __restrict__ dh,
                                     __nv_bfloat16* __restrict__ dl,
                                     int C, int KTB, int out) {
    int i = blockIdx.x * blockDim.x + threadIdx.x;
    if (i >= KF * C * out) return;
    int p = i / (C * out), rem = i % (C * out);
    int k = rem / out, c = rem % out;
    __nv_bfloat16 hi, lo; split2(W[i], hi, lo);
    long long d = ((long long)p * KTB + k) * out + c;
    dh[d] = hi; dl[d] = lo;
}

// ---------------------------------------------------------------------------
// Pipelined bf16-pair GEMM.  C = act( sum_p A_p @ B_p + bias )
// A: [M x Kt] rows (plane stride pstrA), values hi/lo, zero-padded.
// B: [Kt x N] (plane stride pstrB), zero-padded. BM=64, BN=128, BK=64.
// Output: pair (Ch,Cl) or fp32 Cf. blockIdx.z adds aZ/bZ/cZ offsets.
// ---------------------------------------------------------------------------
#define SMEM_A_BYTES 36864            // 2 stages * 2(hl) * 64 * 72 * 2B
#define SMEM_B_BYTES 69632            // 2 stages * 2(hl) * 64 * 136 * 2B
#define SMEM_TOTAL   (SMEM_A_BYTES + SMEM_B_BYTES)

__device__ __forceinline__ void cp16(uint32_t s, const void* g) {
    asm volatile("cp.async.cg.shared.global [%0], [%1], 16;\n" :: "r"(s), "l"(g));
}

__global__ __launch_bounds__(256, 2) void pgemm_kernel(
    int M, int Kt, int ktpp, int nplanes,
    const __nv_bfloat16* __restrict__ Ah, const __nv_bfloat16* __restrict__ Al,
    long long ldaA, long long pstrA, long long aZ,
    const __nv_bfloat16* __restrict__ Bh, const __nv_bfloat16* __restrict__ Bl,
    long long ldbB, long long pstrB, long long bZ,
    float* __restrict__ Cf, __nv_bfloat16* __restrict__ Ch, __nv_bfloat16* __restrict__ Cl,
    long long ldc, long long cZ,
    const float* __restrict__ bias, int act)
{
    extern __shared__ char smem[];
    __nv_bfloat16* sA = (__nv_bfloat16*)smem;
    __nv_bfloat16* sB = (__nv_bfloat16*)(smem + SMEM_A_BYTES);
    const uint32_t sAu = (uint32_t)__cvta_generic_to_shared(sA);
    const uint32_t sBu = (uint32_t)__cvta_generic_to_shared(sB);

    const int tid = threadIdx.x;
    const int w = tid >> 5, lane = tid & 31;
    const int wm = w >> 2, wn = w & 3;      // 2x4 warps, 32x32 tiles
    const int rowBase = blockIdx.y * 64;
    const int colBase = blockIdx.x * 128;

    Ah += (long long)blockIdx.z * aZ;  Al += (long long)blockIdx.z * aZ;
    Bh += (long long)blockIdx.z * bZ;  Bl += (long long)blockIdx.z * bZ;
    if (Ch) { Ch += (long long)blockIdx.z * cZ; Cl += (long long)blockIdx.z * cZ; }
    if (Cf) { Cf += (long long)blockIdx.z * cZ; }

    auto fill = [&](int stage, int it) {
        int p = it / ktpp;
        int k0 = (it - p * ktpp) * 64;
        const __nv_bfloat16* A0h = Ah + (long long)p * pstrA;
        const __nv_bfloat16* A0l = Al + (long long)p * pstrA;
        const __nv_bfloat16* B0h = Bh + (long long)p * pstrB;
        const __nv_bfloat16* B0l = Bl + (long long)p * pstrB;
#pragma unroll
        for (int t = 0; t < 2; ++t) {                 // A: 512 16B chunks per h/l
            int id = tid + t * 256;
            int row = id >> 3, cc = id & 7;
            int k = k0 + cc * 8;
            uint32_t s0 = sAu + (uint32_t)((((stage * 2 + 0) * 64 + row) * 72 + cc * 8) * 2);
            uint32_t s1 = sAu + (uint32_t)((((stage * 2 + 1) * 64 + row) * 72 + cc * 8) * 2);
            if (k < Kt) {
                long long ga = (long long)(rowBase + row) * ldaA + k;
                cp16(s0, A0h + ga);
                cp16(s1, A0l + ga);
            } else {
                float4 z = {0.f, 0.f, 0.f, 0.f};
                *(float4*)(sA + (((stage * 2 + 0) * 64 + row) * 72 + cc * 8)) = z;
                *(float4*)(sA + (((stage * 2 + 1) * 64 + row) * 72 + cc * 8)) = z;
            }
        }
#pragma unroll
        for (int t = 0; t < 4; ++t) {                 // B: 1024 16B chunks per h/l
            int id = tid + t * 256;
            int row = id >> 4, cc = id & 15;
            long long gb = (long long)(k0 + row) * ldbB + colBase + cc * 8;
            uint32_t s0 = sBu + (uint32_t)((((stage * 2 + 0) * 64 + row) * 136 + cc * 8) * 2);
            uint32_t s1 = sBu + (uint32_t)((((stage * 2 + 1) * 64 + row) * 136 + cc * 8) * 2);
            cp16(s0, B0h + gb);
            cp16(s1, B0l + gb);
        }
        asm volatile("cp.async.commit_group;\n" ::: "memory");
    };

    wmma::fragment<wmma::accumulator, 16, 16, 16, float> acc[2][2];
#pragma unroll
    for (int i = 0; i < 2; ++i)
#pragma unroll
        for (int j = 0; j < 2; ++j) wmma::fill_fragment(acc[i][j], 0.f);

    const int T = ktpp * nplanes;
    fill(0, 0);
    for (int it = 0; it < T; ++it) {
        if (it + 1 < T) {
            fill((it + 1) & 1, it + 1);
            asm volatile("cp.async.wait_group 1;\n" ::: "memory");
        } else {
            asm volatile("cp.async.wait_group 0;\n" ::: "memory");
        }
        __syncthreads();
        const int st = it & 1;
#pragma unroll
        for (int kk = 0; kk < 4; ++kk) {
            wmma::fragment<wmma::matrix_a, 16, 16, 16, __nv_bfloat16, wmma::row_major> a_h[2], a_l[2];
            wmma::fragment<wmma::matrix_b, 16, 16, 16, __nv_bfloat16, wmma::row_major> b_h[2], b_l[2];
#pragma unroll
            for (int i = 0; i < 2; ++i) {
                const int r = wm * 32 + i * 16;
                wmma::load_matrix_sync(a_h[i], sA + ((st * 2 + 0) * 64 + r) * 72 + kk * 16, 72);
                wmma::load_matrix_sync(a_l[i], sA + ((st * 2 + 1) * 64 + r) * 72 + kk * 16, 72);
            }
#pragma unroll
            for (int j = 0; j < 2; ++j) {
                const int c = wn * 32 + j * 16;
                wmma::load_matrix_sync(b_h[j], sB + ((st * 2 + 0) * 64 + kk * 16) * 136 + c, 136);
                wmma::load_matrix_sync(b_l[j], sB + ((st * 2 + 1) * 64 + kk * 16) * 136 + c, 136);
            }
#pragma unroll
            for (int i = 0; i < 2; ++i)
#pragma unroll
                for (int j = 0; j < 2; ++j) {
                    wmma::mma_sync(acc[i][j], a_h[i], b_h[j], acc[i][j]);
                    wmma::mma_sync(acc[i][j], a_h[i], b_l[j], acc[i][j]);
                    wmma::mma_sync(acc[i][j], a_l[i], b_h[j], acc[i][j]);
                }
        }
        __syncthreads();
    }

    // ---- epilogue: warp scratch (reuses sA region: 8 * 32*36 floats) ----
    float* scr = (float*)smem + w * (32 * 36);
#pragma unroll
    for (int i = 0; i < 2; ++i)
#pragma unroll
        for (int j = 0; j < 2; ++j)
            wmma::store_matrix_sync(scr + (i * 16) * 36 + j * 16, acc[i][j], 36,
                                    wmma::mem_row_major);
    __syncwarp();

#pragma unroll
    for (int t = 0; t < 16; ++t) {
        int e = lane + t * 32;
        int r = e >> 4, c = (e & 15) * 2;
        int gr = rowBase + wm * 32 + r;
        if (gr >= M) continue;
        int gc = colBase + wn * 32 + c;
        float v0 = scr[r * 36 + c];
        float v1 = scr[r * 36 + c + 1];
        if (bias) { v0 += bias[gc]; v1 += bias[gc + 1]; }
        if (act == 1) { v0 = 1.f / (1.f + expf(-v0)); v1 = 1.f / (1.f + expf(-v1)); }
        else if (act == 2) { v0 = tanhf(v0); v1 = tanhf(v1); }
        if (Ch) {
            __nv_bfloat16 h0, l0, h1, l1;
            split2(v0, h0, l0); split2(v1, h1, l1);
            __nv_bfloat162 hh; hh.x = h0; hh.y = h1;
            __nv_bfloat162 ll; ll.x = l0; ll.y = l1;
            *(__nv_bfloat162*)&Ch[(long long)gr * ldc + gc] = hh;
            *(__nv_bfloat162*)&Cl[(long long)gr * ldc + gc] = ll;
        } else {
            float2 f; f.x = v0; f.y = v1;
            *(float2*)&Cf[(long long)gr * ldc + gc] = f;
        }
    }
}

// ---------------------------------------------------------------------------
// Build plane 0 of feats (hi/lo): [x, (r*)h], zeros in pad columns.
// ---------------------------------------------------------------------------
__global__ void concat_kernel(__nv_bfloat16* __restrict__ ph,
                              __nv_bfloat16* __restrict__ pl,
                              const float* __restrict__ xsrc, int xmode, int t,
                              int Cx, int C, int Cp,
                              const float* __restrict__ h,
                              const float* __restrict__ gates, int useR)
{
    const long long total = (long long)NN * BB * Cp;
    for (long long i = blockIdx.x * (long long)blockDim.x + threadIdx.x; i < total;
         i += (long long)gridDim.x * blockDim.x) {
        int c  = (int)(i % Cp);
        int nb = (int)(i / Cp);
        float v = 0.f;
        if (c < Cx) {
            if (xmode == 0) {
                int b = nb % BB, n = nb / BB;
                v = xsrc[(((long long)b * TT + t) * NN + n) * DIN + c];
            } else {
                v = xsrc[(long long)nb * Cx + c];
            }
        } else if (c < C) {
            int hc = c - Cx;
            float hv = h[(long long)nb * HH + hc];
            if (useR) hv *= gates[(long long)nb * (2 * HH) + HH + hc];
            v = hv;
        }
        __nv_bfloat16 hi, lo; split2(v, hi, lo);
        ph[i] = hi; pl[i] = lo;
    }
}

__global__ void gru_update_kernel(float* __restrict__ h,
                                  const float* __restrict__ gates,
                                  const float* __restrict__ hcb)
{
    int i = blockIdx.x * blockDim.x + threadIdx.x;
    if (i >= NN * BB * HH) return;
    int row = i / HH, c = i % HH;
    float z = gates[(long long)row * (2 * HH) + c];
    h[i] = z * h[i] + (1.f - z) * hcb[i];
}

__global__ void dec_proj_kernel(const float* __restrict__ h1,
                                const float* __restrict__ Wp,
                                const float* __restrict__ bp,
                                float* __restrict__ out,
                                float* __restrict__ xdec, int t)
{
    int row = blockIdx.x * blockDim.x + threadIdx.x;
    if (row >= NN * BB) return;
    int n = row / BB, b = row % BB;
    float a0 = bp[0], a1 = bp[1];
    const float* hr = h1 + (long long)row * HH;
#pragma unroll 8
    for (int k = 0; k < HH; ++k) {
        float hv = hr[k];
        a0 += hv * Wp[k * 2 + 0];
        a1 += hv * Wp[k * 2 + 1];
    }
    long long o = (((long long)b * TT + t) * NN + n) * 2;
    out[o] = a0; out[o + 1] = a1;
    xdec[(long long)row * 2] = a0;
    xdec[(long long)row * 2 + 1] = a1;
}

__global__ void zero_kernel(float* __restrict__ p, long long n)
{
    for (long long i = blockIdx.x * (long long)blockDim.x + threadIdx.x; i < n;
         i += (long long)gridDim.x * blockDim.x)
        p[i] = 0.f;
}

// ---------------------------------------------------------------------------
// Host orchestration
// ---------------------------------------------------------------------------
static inline int gblocks(long long total, int tpb) {
    long long b = (total + tpb - 1) / tpb;
    if (b > 1048576) b = 1048576;
    return (int)b;
}

struct CellW {
    const __nv_bfloat16 *wgh, *wgl, *wch, *wcl;
    const float *bg, *bc;
    int Cx, C, Cp, ktpp, KTB;
    __nv_bfloat16 *fh, *fl;
    long long pstr;
};

static void run_cell(const float* xsrc, int xmode, int t, float* h,
                     const CellW& cw, float* gates, float* hcb)
{
    const int Cp = cw.Cp;
    const int ldN = BB * Cp;
    const long long PS = cw.pstr;
    const long long SUPZ = 384LL * 384;
    const long long totalC = (long long)NN * BB * Cp;

    dim3 gd(ldN / 128, 6, 2);

    auto diffuse = [&](const __nv_bfloat16* srcH, const __nv_bfloat16* srcL,
                       long long bZ, __nv_bfloat16* dstH, __nv_bfloat16* dstL) {
        pgemm_kernel<<<gd, 256, SMEM_TOTAL>>>(
            NN, 384, 6, 1,
            g_sh_p, g_sl_p, 384, 0, SUPZ,
            srcH, srcL, ldN, 0, bZ,
            nullptr, dstH, dstL, ldN, 2 * PS,
            nullptr, 0);
    };

    // ---- gate gconv ----
    concat_kernel<<<gblocks(totalC, 256), 256>>>(cw.fh, cw.fl, xsrc, xmode, t,
                                                 cw.Cx, cw.C, Cp, h, nullptr, 0);
    diffuse(cw.fh, cw.fl, 0, cw.fh + PS, cw.fl + PS);
    diffuse(cw.fh + PS, cw.fl + PS, 2 * PS, cw.fh + 2 * PS, cw.fl + 2 * PS);
    {
        dim3 g(2, NB / 64, 1);
        pgemm_kernel<<<g, 256, SMEM_TOTAL>>>(
            NB, Cp, cw.ktpp, KF,
            cw.fh, cw.fl, Cp, PS, 0,
            cw.wgh, cw.wgl, 2 * HH, (long long)cw.KTB * 2 * HH, 0,
            gates, nullptr, nullptr, 2 * HH, 0,
            cw.bg, 1);
    }

    // ---- candidate gconv ----
    concat_kernel<<<gblocks(totalC, 256), 256>>>(cw.fh, cw.fl, xsrc, xmode, t,
                                                 cw.Cx, cw.C, Cp, h, gates, 1);
    diffuse(cw.fh, cw.fl, 0, cw.fh + PS, cw.fl + PS);
    diffuse(cw.fh + PS, cw.fl + PS, 2 * PS, cw.fh + 2 * PS, cw.fl + 2 * PS);
    {
        dim3 g(1, NB / 64, 1);
        pgemm_kernel<<<g, 256, SMEM_TOTAL>>>(
            NB, Cp, cw.ktpp, KF,
            cw.fh, cw.fl, Cp, PS, 0,
            cw.wch, cw.wcl, HH, (long long)cw.KTB * HH, 0,
            hcb, nullptr, nullptr, HH, 0,
            cw.bc, 2);
    }

    gru_update_kernel<<<gblocks((long long)NB * HH, 256), 256>>>(h, gates, hcb);
}

extern "C" void kernel_launch(void* const* d_in, const int* in_sizes, int n_in,
                              void* d_out, int out_size)
{
    const float* source   = (const float*)d_in[0];
    const float* supports = (const float*)d_in[2];
    const float* Wp = (const float*)d_in[19];
    const float* bp = (const float*)d_in[20];
    float* out = (float*)d_out;

    cudaFuncSetAttribute(pgemm_kernel, cudaFuncAttributeMaxDynamicSharedMemorySize,
                         SMEM_TOTAL);

    __nv_bfloat16 *f0h, *f0l, *f1h, *f1l, *wh, *wl;
    float *gates, *hcb, *h0, *h1, *xdec;
    cudaGetSymbolAddress((void**)&f0h, g_f0h);
    cudaGetSymbolAddress((void**)&f0l, g_f0l);
    cudaGetSymbolAddress((void**)&f1h, g_f1h);
    cudaGetSymbolAddress((void**)&f1l, g_f1l);
    cudaGetSymbolAddress((void**)&g_sh_p, g_sh);
    cudaGetSymbolAddress((void**)&g_sl_p, g_sl);
    cudaGetSymbolAddress((void**)&wh, g_wh);
    cudaGetSymbolAddress((void**)&wl, g_wl);
    cudaGetSymbolAddress((void**)&gates, g_gates);
    cudaGetSymbolAddress((void**)&hcb, g_hc);
    cudaGetSymbolAddress((void**)&h0, g_h0);
    cudaGetSymbolAddress((void**)&h1, g_h1);
    cudaGetSymbolAddress((void**)&xdec, g_xdec);

    // ---- prep: split supports + weights to bf16 pairs (captured, cheap) ----
    split_supports_kernel<<<gblocks(2LL * NN * NN, 256), 256>>>(supports);
    struct WSpec { int in_idx, off, C, KTB, out; };
    const WSpec ws[8] = {
        {3,  OFF_E0G, 130, KTB0, 256}, {5,  OFF_E0C, 130, KTB0, 128},
        {7,  OFF_E1G, 256, KTB1, 256}, {9,  OFF_E1C, 256, KTB1, 128},
        {11, OFF_D0G, 130, KTB0, 256}, {13, OFF_D0C, 130, KTB0, 128},
        {15, OFF_D1G, 256, KTB1, 256}, {17, OFF_D1C, 256, KTB1, 128},
    };
    for (int i = 0; i < 8; ++i) {
        long long n = (long long)KF * ws[i].C * ws[i].out;
        split_weights_kernel<<<gblocks(n, 256), 256>>>(
            (const float*)d_in[ws[i].in_idx], wh + ws[i].off, wl + ws[i].off,
            ws[i].C, ws[i].KTB, ws[i].out);
    }

    zero_kernel<<<gblocks((long long)NB * HH, 256), 256>>>(h0, (long long)NB * HH);
    zero_kernel<<<gblocks((long long)NB * HH, 256), 256>>>(h1, (long long)NB * HH);
    zero_kernel<<<gblocks((long long)NB * DIN, 256), 256>>>(xdec, (long long)NB * DIN);

    CellW enc0{ wh + OFF_E0G, wl + OFF_E0G, wh + OFF_E0C, wl + OFF_E0C,
                (const float*)d_in[4],  (const float*)d_in[6],
                DIN, DIN + HH, CP0, 3, KTB0, f0h, f0l, PSTR0 };
    CellW enc1{ wh + OFF_E1G, wl + OFF_E1G, wh + OFF_E1C, wl + OFF_E1C,
                (const float*)d_in[8],  (const float*)d_in[10],
                HH, 2 * HH, CP1, 4, KTB1, f1h, f1l, PSTR1 };
    CellW dec0{ wh + OFF_D0G, wl + OFF_D0G, wh + OFF_D0C, wl + OFF_D0C,
                (const float*)d_in[12], (const float*)d_in[14],
                DIN, DIN + HH, CP0, 3, KTB0, f0h, f0l, PSTR0 };
    CellW dec1{ wh + OFF_D1G, wl + OFF_D1G, wh + OFF_D1C, wl + OFF_D1C,
                (const float*)d_in[16], (const float*)d_in[18],
                HH, 2 * HH, CP1, 4, KTB1, f1h, f1l, PSTR1 };

    for (int t = 0; t < TT; ++t) {
        run_cell(source, 0, t, h0, enc0, gates, hcb);
        run_cell(h0,     1, t, h1, enc1, gates, hcb);
    }
    for (int t = 0; t < TT; ++t) {
        run_cell(xdec, 1, t, h0, dec0, gates, hcb);
        run_cell(h0,   1, t, h1, dec1, gates, hcb);
        dec_proj_kernel<<<(NB + 255) / 256, 256>>>(h1, Wp, bp, out, xdec, t);
    }
}